// round 10
// baseline (speedup 1.0000x reference)
#include <cuda_runtime.h>
#include <cuda_fp16.h>
#include <cstdint>

#define NTOK 16384
#define HDIM 1024
#define MDIM 512
#define NEXP 8
#define MAX_TILES 144
#define KC 64                  // K elements per chunk
#define NCK (HDIM / KC)        // 16 chunks
#define ROWB 144               // padded row bytes (64 fp16 = 128B + 16 pad)
#define A_TB (128 * ROWB)      // A tile bytes 18432
#define B_TB (256 * ROWB)      // B tile bytes 36864
#define STAGE (A_TB + B_TB)    // 55296
#define MAXFLAG 4096
#define GAP_THRESH 4e-3f

// ---------------- scratch ----------------
__device__ __half g_X1[NTOK * HDIM];
__device__ __half g_W1a[MDIM * HDIM];
__device__ __half g_W2a[NEXP * HDIM * HDIM];
__device__ float g_score[NTOK * NEXP];
__device__ int g_idx[NTOK];
__device__ int g_counts[NEXP];
__device__ int g_base[NEXP];
__device__ int g_cursor[NEXP];
__device__ int g_perm[NTOK];
__device__ int g_tile_e[MAX_TILES];
__device__ int g_tile_r[MAX_TILES];
__device__ int g_tile_n[MAX_TILES];
__device__ int g_numtiles;
__device__ int g_flag[MAXFLAG];
__device__ int g_nflag;

// ---------------- helpers ----------------
__device__ __forceinline__ uint32_t smem_u32(const void* p) {
    uint32_t a;
    asm("{ .reg .u64 t; cvta.to.shared.u64 t, %1; cvt.u32.u64 %0, t; }" : "=r"(a) : "l"(p));
    return a;
}
__device__ __forceinline__ void cp16(uint32_t s, const void* g) {
    asm volatile("cp.async.cg.shared.global [%0], [%1], 16;" :: "r"(s), "l"(g));
}
#define CP_COMMIT() asm volatile("cp.async.commit_group;" ::: "memory")
#define CP_WAIT1()  asm volatile("cp.async.wait_group 1;" ::: "memory")
__device__ __forceinline__ void ldsm4(uint32_t r[4], uint32_t a) {
    asm volatile("ldmatrix.sync.aligned.m8n8.x4.shared.b16 {%0,%1,%2,%3}, [%4];"
                 : "=r"(r[0]), "=r"(r[1]), "=r"(r[2]), "=r"(r[3]) : "r"(a));
}
__device__ __forceinline__ void mma16816(float c[4], const uint32_t a[4], const uint32_t b[2]) {
    asm volatile(
        "mma.sync.aligned.m16n8k16.row.col.f32.f16.f16.f32 "
        "{%0,%1,%2,%3}, {%4,%5,%6,%7}, {%8,%9}, {%0,%1,%2,%3};"
        : "+f"(c[0]), "+f"(c[1]), "+f"(c[2]), "+f"(c[3])
        : "r"(a[0]), "r"(a[1]), "r"(a[2]), "r"(a[3]), "r"(b[0]), "r"(b[1]));
}

// ---------------- init ----------------
__global__ void k_init() {
    int t = threadIdx.x;
    if (t < NEXP) { g_counts[t] = 0; g_cursor[t] = 0; }
    if (t == 0) g_nflag = 0;
}
__global__ void k_zeroscore() {
    int i = blockIdx.x * 256 + threadIdx.x;
    ((float4*)g_score)[i] = make_float4(0.f, 0.f, 0.f, 0.f);
}

// ---------------- conversions ----------------
__global__ __launch_bounds__(256) void k_convA(const float* __restrict__ X) {
    int i = blockIdx.x * 256 + threadIdx.x;
    float4 v = ((const float4*)X)[i];
    __align__(8) __half a1[4];
    a1[0] = __float2half_rn(v.x); a1[1] = __float2half_rn(v.y);
    a1[2] = __float2half_rn(v.z); a1[3] = __float2half_rn(v.w);
    ((uint2*)g_X1)[i] = *(uint2*)a1;
}
__global__ void k_convW1(const float* __restrict__ src) {
    __shared__ float t[32][33];
    int n0 = blockIdx.x * 32, k0 = blockIdx.y * 32;
    int tx = threadIdx.x, ty = threadIdx.y;
#pragma unroll
    for (int j = 0; j < 4; j++)
        t[ty + 8 * j][tx] = src[(size_t)(k0 + ty + 8 * j) * MDIM + n0 + tx];
    __syncthreads();
#pragma unroll
    for (int j = 0; j < 4; j++) {
        int rr = ty + 8 * j;
        g_W1a[(size_t)(n0 + rr) * HDIM + k0 + tx] = __float2half_rn(t[tx][rr]);
    }
}
__global__ void k_convW2(const float* __restrict__ src) {
    __shared__ float t[32][33];
    int e = blockIdx.z;
    const float* s = src + ((size_t)e << 20);
    __half* d1 = g_W2a + ((size_t)e << 20);
    int n0 = blockIdx.x * 32, k0 = blockIdx.y * 32;
    int tx = threadIdx.x, ty = threadIdx.y;
#pragma unroll
    for (int j = 0; j < 4; j++)
        t[ty + 8 * j][tx] = s[(size_t)(k0 + ty + 8 * j) * HDIM + n0 + tx];
    __syncthreads();
#pragma unroll
    for (int j = 0; j < 4; j++) {
        int rr = ty + 8 * j;
        d1[(size_t)(n0 + rr) * HDIM + k0 + tx] = __float2half_rn(t[tx][rr]);
    }
}

// ---------------- fp16 GEMM: CTA 128x256, warp 64x64, 2-stage cp.async -------
// !GATHER: gemm1 -> fused routing scores into g_score (no dense output)
//  GATHER: gemm2 -> scattered expert output rows
template <bool GATHER>
__global__ __launch_bounds__(256, 1) void k_gemm_mma(const float* __restrict__ biasg,
                                                     const float* __restrict__ w2g,
                                                     float* __restrict__ outg) {
    __shared__ float sbias[256];
    __shared__ int tks[128];
    __shared__ float sw2[256 * NEXP];
    extern __shared__ char dsm[];
    const uint32_t sb = smem_u32(dsm);

    const int tid = threadIdx.x;
    const int wid = tid >> 5;
    const int lane = tid & 31;
    const int warp_m = wid >> 2;   // 0..1
    const int warp_n = wid & 3;    // 0..3

    int row0 = 0, nrows = 128;
    const int col0 = blockIdx.y * 256;
    const __half *A1, *B1;
    if (GATHER) {
        const int tile = blockIdx.x;
        if (tile >= g_numtiles) return;
        const int e = g_tile_e[tile];
        const int grs = g_tile_r[tile];
        nrows = g_tile_n[tile];
        if (tid < 128) tks[tid] = g_perm[grs + (tid < nrows ? tid : 0)];
        sbias[tid] = biasg[(size_t)e * HDIM + col0 + tid];
        A1 = g_X1;
        B1 = g_W2a + ((size_t)e << 20) + (size_t)col0 * HDIM;
    } else {
        row0 = blockIdx.x * 128;
        sbias[tid] = biasg[col0 + tid];
#pragma unroll
        for (int i = 0; i < 8; i++) sw2[tid * 8 + i] = w2g[(size_t)(col0 + tid) * NEXP + i];
        A1 = g_X1;
        B1 = g_W1a + (size_t)col0 * HDIM;
    }
    __syncthreads();

    auto issue = [&](int buf, int kbase) {
#pragma unroll
        for (int i = 0; i < 12; i++) {
            const int cid = tid + i * 256;         // 0..3071
            const bool isA = cid < 1024;
            const int row = (isA ? cid : cid - 1024) >> 3;
            const int seg = cid & 7;
            uint32_t sa = sb + buf * STAGE + (isA ? 0 : A_TB) + row * ROWB + seg * 16;
            const __half* src = isA ? A1 : B1;
            int grow = isA ? (GATHER ? tks[row] : row0 + row) : row;
            cp16(sa, src + (size_t)grow * HDIM + kbase + seg * 8);
        }
    };

    float acc[4][8][4];
#pragma unroll
    for (int mi = 0; mi < 4; mi++)
#pragma unroll
        for (int ni = 0; ni < 8; ni++)
#pragma unroll
            for (int k = 0; k < 4; k++) acc[mi][ni][k] = 0.0f;

    issue(0, 0);  CP_COMMIT();
    issue(1, KC); CP_COMMIT();

    const int lm = lane & 15, lh = lane >> 4;
    const uint32_t a_off = (uint32_t)((warp_m * 64 + lm) * ROWB + lh * 16);
    const uint32_t b_off = (uint32_t)((warp_n * 64 + lm) * ROWB + lh * 16);

    for (int c = 0; c < NCK; c++) {
        CP_WAIT1();
        __syncthreads();
        const int buf = c & 1;
        const uint32_t sA1 = sb + buf * STAGE;
        const uint32_t sB1 = sA1 + A_TB;

#pragma unroll
        for (int kh = 0; kh < 4; kh++) {
            uint32_t a1[4][4], b1f[8][2];
#pragma unroll
            for (int mi = 0; mi < 4; mi++)
                ldsm4(a1[mi], sA1 + a_off + mi * (16 * ROWB) + kh * 32);
#pragma unroll
            for (int nt = 0; nt < 4; nt++) {
                uint32_t r[4];
                ldsm4(r, sB1 + b_off + nt * (16 * ROWB) + kh * 32);
                b1f[nt * 2][0] = r[0]; b1f[nt * 2][1] = r[2];
                b1f[nt * 2 + 1][0] = r[1]; b1f[nt * 2 + 1][1] = r[3];
            }
#pragma unroll
            for (int mi = 0; mi < 4; mi++)
#pragma unroll
                for (int ni = 0; ni < 8; ni++)
                    mma16816(acc[mi][ni], a1[mi], b1f[ni]);
        }
        __syncthreads();
        if (c + 2 < NCK) issue(buf, (c + 2) * KC);
        CP_COMMIT();
    }

    // ---------------- epilogue ----------------
    const int rbase = warp_m * 64 + (lane >> 2);
    const int cbase = warp_n * 64 + (lane & 3) * 2;
    if (GATHER) {
#pragma unroll
        for (int mi = 0; mi < 4; mi++) {
#pragma unroll
            for (int ni = 0; ni < 8; ni++) {
                const int r0 = rbase + mi * 16;
                const int cc = cbase + ni * 8;
                float v00 = acc[mi][ni][0] + sbias[cc];
                float v01 = acc[mi][ni][1] + sbias[cc + 1];
                float v10 = acc[mi][ni][2] + sbias[cc];
                float v11 = acc[mi][ni][3] + sbias[cc + 1];
                if (r0 < nrows) {
                    float* p = outg + (size_t)tks[r0] * HDIM + col0 + cc;
                    *(float2*)p = make_float2(v00, v01);
                }
                if (r0 + 8 < nrows) {
                    float* p = outg + (size_t)tks[r0 + 8] * HDIM + col0 + cc;
                    *(float2*)p = make_float2(v10, v11);
                }
            }
        }
    } else {
        // fused routing-score epilogue: relu(acc + b1) dot w2-slice -> atomic
#pragma unroll
        for (int mi = 0; mi < 4; mi++) {
#pragma unroll
            for (int ro = 0; ro < 2; ro++) {
                const int row = rbase + mi * 16 + ro * 8;
                float part[NEXP];
#pragma unroll
                for (int e = 0; e < NEXP; e++) part[e] = 0.0f;
#pragma unroll
                for (int ni = 0; ni < 8; ni++) {
                    const int cc = cbase + ni * 8;
                    float v0 = fmaxf(acc[mi][ni][ro * 2 + 0] + sbias[cc], 0.0f);
                    float v1 = fmaxf(acc[mi][ni][ro * 2 + 1] + sbias[cc + 1], 0.0f);
#pragma unroll
                    for (int e = 0; e < NEXP; e++)
                        part[e] = fmaf(v0, sw2[cc * 8 + e], fmaf(v1, sw2[(cc + 1) * 8 + e], part[e]));
                }
#pragma unroll
                for (int e = 0; e < NEXP; e++) {
                    part[e] += __shfl_xor_sync(0xffffffffu, part[e], 1);
                    part[e] += __shfl_xor_sync(0xffffffffu, part[e], 2);
                }
                if ((lane & 3) == 0) {
#pragma unroll
                    for (int e = 0; e < NEXP; e++)
                        atomicAdd(&g_score[(size_t)(row0 + row) * NEXP + e], part[e]);
                }
            }
        }
    }
}

// ---------------- argmax + counts + near-tie flagging ----------------
__global__ __launch_bounds__(256) void k_argmax(const float* __restrict__ b2) {
    const int t = blockIdx.x * 256 + threadIdx.x;
    if (t >= NTOK) return;
    const float* sr = g_score + (size_t)t * NEXP;
    int best = 0;
    float bv = sr[0] + b2[0], second = -1e30f;
#pragma unroll
    for (int e = 1; e < NEXP; e++) {
        float v = sr[e] + b2[e];
        if (v > bv) { second = bv; bv = v; best = e; }
        else if (v > second) second = v;
    }
    g_idx[t] = best;
    atomicAdd(&g_counts[best], 1);
    if (bv - second < GAP_THRESH) {
        int slot = atomicAdd(&g_nflag, 1);
        if (slot < MAXFLAG) g_flag[slot] = t;
    }
}

// ---------------- exact fp32 rescue (one block per flagged token, ILP4) ------
__global__ __launch_bounds__(256) void k_rescue(const float* __restrict__ X,
                                                const float* __restrict__ w1,
                                                const float* __restrict__ b1,
                                                const float* __restrict__ w2,
                                                const float* __restrict__ b2) {
    __shared__ float sx[HDIM];
    __shared__ float ssc[NEXP];
    const int tid = threadIdx.x;
    int n = g_nflag;
    if (n > MAXFLAG) n = MAXFLAG;
    for (int i = blockIdx.x; i < n; i += gridDim.x) {
        const int tok = g_flag[i];
        for (int k = tid; k < HDIM; k += 256) sx[k] = X[(size_t)tok * HDIM + k];
        if (tid < NEXP) ssc[tid] = 0.0f;
        __syncthreads();
        float sc[NEXP];
#pragma unroll
        for (int e = 0; e < NEXP; e++) sc[e] = 0.0f;
#pragma unroll
        for (int half = 0; half < 2; half++) {
            const int nc = tid + half * 256;
            float a0 = 0.f, a1 = 0.f, a2 = 0.f, a3 = 0.f;
#pragma unroll 4
            for (int k = 0; k < HDIM; k += 4) {
                a0 = fmaf(sx[k + 0], __ldg(&w1[(size_t)(k + 0) * MDIM + nc]), a0);
                a1 = fmaf(sx[k + 1], __ldg(&w1[(size_t)(k + 1) * MDIM + nc]), a1);
                a2 = fmaf(sx[k + 2], __ldg(&w1[(size_t)(k + 2) * MDIM + nc]), a2);
                a3 = fmaf(sx[k + 3], __ldg(&w1[(size_t)(k + 3) * MDIM + nc]), a3);
            }
            float a = fmaxf((a0 + a1) + (a2 + a3) + b1[nc], 0.0f);
#pragma unroll
            for (int e = 0; e < NEXP; e++) sc[e] = fmaf(a, w2[nc * NEXP + e], sc[e]);
        }
#pragma unroll
        for (int e = 0; e < NEXP; e++) {
#pragma unroll
            for (int off = 16; off; off >>= 1) sc[e] += __shfl_xor_sync(0xffffffffu, sc[e], off);
            if ((tid & 31) == 0) atomicAdd(&ssc[e], sc[e]);
        }
        __syncthreads();
        if (tid == 0) {
            int best = 0;
            float bv = ssc[0] + b2[0];
#pragma unroll
            for (int e = 1; e < NEXP; e++) {
                float v = ssc[e] + b2[e];
                if (v > bv) { bv = v; best = e; }
            }
            int old = g_idx[tok];
            if (best != old) {
                g_idx[tok] = best;
                atomicSub(&g_counts[old], 1);
                atomicAdd(&g_counts[best], 1);
            }
        }
        __syncthreads();
    }
}

// ---------------- scan + fill ----------------
__global__ void k_scan() {
    int s = 0;
    for (int e = 0; e < NEXP; e++) { g_base[e] = s; s += g_counts[e]; }
    int nt = 0;
    for (int e = 0; e < NEXP; e++) {
        int c = g_counts[e];
        for (int r = 0; r < c; r += 128) {
            g_tile_e[nt] = e;
            g_tile_r[nt] = g_base[e] + r;
            g_tile_n[nt] = (c - r) < 128 ? (c - r) : 128;
            nt++;
        }
    }
    g_numtiles = nt;
}
__global__ void k_fill() {
    int t = blockIdx.x * 256 + threadIdx.x;
    if (t < NTOK) {
        int e = g_idx[t];
        int r = atomicAdd(&g_cursor[e], 1);
        g_perm[g_base[e] + r] = t;
    }
}

// ---------------- launch ----------------
extern "C" void kernel_launch(void* const* d_in, const int* in_sizes, int n_in,
                              void* d_out, int out_size) {
    const float* X  = (const float*)d_in[0];
    const float* w1 = (const float*)d_in[1];
    const float* b1 = (const float*)d_in[2];
    const float* w2 = (const float*)d_in[3];
    const float* b2 = (const float*)d_in[4];
    const float* eW = (const float*)d_in[5];
    const float* eb = (const float*)d_in[6];
    float* out = (float*)d_out;

    const int DSM = 2 * STAGE;  // 110592
    cudaFuncSetAttribute(k_gemm_mma<false>, cudaFuncAttributeMaxDynamicSharedMemorySize, DSM);
    cudaFuncSetAttribute(k_gemm_mma<true>,  cudaFuncAttributeMaxDynamicSharedMemorySize, DSM);

    k_init<<<1, 32>>>();
    k_zeroscore<<<NTOK * NEXP / 4 / 256, 256>>>();
    k_convA<<<NTOK * HDIM / 1024, 256>>>(X);
    k_convW1<<<dim3(MDIM / 32, HDIM / 32, 1), dim3(32, 8)>>>(w1);
    k_convW2<<<dim3(HDIM / 32, HDIM / 32, NEXP), dim3(32, 8)>>>(eW);
    k_gemm_mma<false><<<dim3(NTOK / 128, MDIM / 256), 256, DSM>>>(b1, w2, nullptr);
    k_argmax<<<NTOK / 256, 256>>>(b2);
    k_rescue<<<256, 256>>>(X, w1, b1, w2, b2);
    k_scan<<<1, 1>>>();
    k_fill<<<NTOK / 256, 256>>>();
    k_gemm_mma<true><<<dim3(MAX_TILES, HDIM / 256), 256, DSM>>>(eb, nullptr, out);
}

// round 11
// speedup vs baseline: 1.0598x; 1.0598x over previous
#include <cuda_runtime.h>
#include <cuda_fp16.h>
#include <cstdint>

#define NTOK 16384
#define HDIM 1024
#define MDIM 512
#define NEXP 8
#define MAX_TILES 144
#define KC 64                 // K elements per chunk
#define NCK (HDIM / KC)       // 16 chunks
#define ROWB 144              // padded row bytes (64 fp16 = 128B + 16 pad)
#define TILEB (128 * ROWB)    // 18432
#define MAXFLAG 4096
#define GAP_THRESH 4e-3f

// ---------------- scratch ----------------
__device__ __half g_X1[NTOK * HDIM];
__device__ __half g_W1a[MDIM * HDIM];
__device__ __half g_W2a[NEXP * HDIM * HDIM];
__device__ float g_score[NTOK * NEXP];
__device__ int g_idx[NTOK];
__device__ int g_counts[NEXP];
__device__ int g_base[NEXP];
__device__ int g_cursor[NEXP];
__device__ int g_perm[NTOK];
__device__ int g_tile_e[MAX_TILES];
__device__ int g_tile_r[MAX_TILES];
__device__ int g_tile_n[MAX_TILES];
__device__ int g_numtiles;
__device__ int g_flag[MAXFLAG];
__device__ int g_nflag;

// ---------------- helpers ----------------
__device__ __forceinline__ uint32_t smem_u32(const void* p) {
    uint32_t a;
    asm("{ .reg .u64 t; cvta.to.shared.u64 t, %1; cvt.u32.u64 %0, t; }" : "=r"(a) : "l"(p));
    return a;
}
__device__ __forceinline__ void cp16(uint32_t s, const void* g) {
    asm volatile("cp.async.cg.shared.global [%0], [%1], 16;" :: "r"(s), "l"(g));
}
#define CP_COMMIT() asm volatile("cp.async.commit_group;" ::: "memory")
#define CP_WAIT1()  asm volatile("cp.async.wait_group 1;" ::: "memory")
__device__ __forceinline__ void ldsm4(uint32_t r[4], uint32_t a) {
    asm volatile("ldmatrix.sync.aligned.m8n8.x4.shared.b16 {%0,%1,%2,%3}, [%4];"
                 : "=r"(r[0]), "=r"(r[1]), "=r"(r[2]), "=r"(r[3]) : "r"(a));
}
__device__ __forceinline__ void mma16816(float c[4], const uint32_t a[4], const uint32_t b[2]) {
    asm volatile(
        "mma.sync.aligned.m16n8k16.row.col.f32.f16.f16.f32 "
        "{%0,%1,%2,%3}, {%4,%5,%6,%7}, {%8,%9}, {%0,%1,%2,%3};"
        : "+f"(c[0]), "+f"(c[1]), "+f"(c[2]), "+f"(c[3])
        : "r"(a[0]), "r"(a[1]), "r"(a[2]), "r"(a[3]), "r"(b[0]), "r"(b[1]));
}

// ---------------- init ----------------
__global__ void k_init() {
    int t = threadIdx.x;
    if (t < NEXP) { g_counts[t] = 0; g_cursor[t] = 0; }
    if (t == 0) g_nflag = 0;
}
__global__ void k_zeroscore() {
    int i = blockIdx.x * 256 + threadIdx.x;
    ((float4*)g_score)[i] = make_float4(0.f, 0.f, 0.f, 0.f);
}

// ---------------- conversions ----------------
__global__ __launch_bounds__(256) void k_convA(const float* __restrict__ X) {
    int i = blockIdx.x * 256 + threadIdx.x;
    float4 v = ((const float4*)X)[i];
    __align__(8) __half a1[4];
    a1[0] = __float2half_rn(v.x); a1[1] = __float2half_rn(v.y);
    a1[2] = __float2half_rn(v.z); a1[3] = __float2half_rn(v.w);
    ((uint2*)g_X1)[i] = *(uint2*)a1;
}
__global__ void k_convW1(const float* __restrict__ src) {
    __shared__ float t[32][33];
    int n0 = blockIdx.x * 32, k0 = blockIdx.y * 32;
    int tx = threadIdx.x, ty = threadIdx.y;
#pragma unroll
    for (int j = 0; j < 4; j++)
        t[ty + 8 * j][tx] = src[(size_t)(k0 + ty + 8 * j) * MDIM + n0 + tx];
    __syncthreads();
#pragma unroll
    for (int j = 0; j < 4; j++) {
        int rr = ty + 8 * j;
        g_W1a[(size_t)(n0 + rr) * HDIM + k0 + tx] = __float2half_rn(t[tx][rr]);
    }
}
__global__ void k_convW2(const float* __restrict__ src) {
    __shared__ float t[32][33];
    int e = blockIdx.z;
    const float* s = src + ((size_t)e << 20);
    __half* d1 = g_W2a + ((size_t)e << 20);
    int n0 = blockIdx.x * 32, k0 = blockIdx.y * 32;
    int tx = threadIdx.x, ty = threadIdx.y;
#pragma unroll
    for (int j = 0; j < 4; j++)
        t[ty + 8 * j][tx] = s[(size_t)(k0 + ty + 8 * j) * HDIM + n0 + tx];
    __syncthreads();
#pragma unroll
    for (int j = 0; j < 4; j++) {
        int rr = ty + 8 * j;
        d1[(size_t)(n0 + rr) * HDIM + k0 + tx] = __float2half_rn(t[tx][rr]);
    }
}

// ---------------- fp16 GEMM: CTA 128x128, warp 64x32, KC=64, 2-stage ---------
// !GATHER: gemm1 -> fused routing scores into g_score (no dense hidden output)
//  GATHER: gemm2 -> scattered expert output rows
template <bool GATHER>
__global__ __launch_bounds__(256, 2) void k_gemm_mma(const float* __restrict__ biasg,
                                                     const float* __restrict__ w2g,
                                                     float* __restrict__ outg) {
    constexpr int STAGE = 2 * TILEB;     // A + B
    __shared__ float sbias[128];
    __shared__ int tks[128];
    __shared__ float sw2[128 * NEXP];    // gemm1 only
    extern __shared__ char dsm[];
    const uint32_t sb = smem_u32(dsm);

    const int tid = threadIdx.x;
    const int wid = tid >> 5;
    const int lane = tid & 31;
    const int warp_m = wid >> 2;   // 0..1
    const int warp_n = wid & 3;    // 0..3

    int row0 = 0, nrows = 128;
    const int col0 = blockIdx.y * 128;
    const __half *A1, *B1;
    if (GATHER) {
        const int tile = blockIdx.x;
        if (tile >= g_numtiles) return;
        const int e = g_tile_e[tile];
        const int grs = g_tile_r[tile];
        nrows = g_tile_n[tile];
        if (tid < 128) {
            tks[tid] = g_perm[grs + (tid < nrows ? tid : 0)];
            sbias[tid] = biasg[(size_t)e * HDIM + col0 + tid];
        }
        A1 = g_X1;
        B1 = g_W2a + ((size_t)e << 20) + (size_t)col0 * HDIM;
    } else {
        row0 = blockIdx.x * 128;
        if (tid < 128) {
            sbias[tid] = biasg[col0 + tid];
#pragma unroll
            for (int e = 0; e < NEXP; e++)
                sw2[tid * NEXP + e] = w2g[(size_t)(col0 + tid) * NEXP + e];
        }
        A1 = g_X1;
        B1 = g_W1a + (size_t)col0 * HDIM;
    }
    __syncthreads();

    // cp.async mapping: 2048 chunks of 16B per stage, 8 per thread
    int c_tile[8], c_row[8], c_seg[8];
#pragma unroll
    for (int i = 0; i < 8; i++) {
        int cid = tid + i * 256;
        c_tile[i] = cid >> 10;
        c_row[i] = (cid >> 3) & 127;
        c_seg[i] = cid & 7;
    }

    auto issue = [&](int buf, int kbase) {
#pragma unroll
        for (int i = 0; i < 8; i++) {
            const int tile = c_tile[i], row = c_row[i], seg = c_seg[i];
            uint32_t sa = sb + buf * STAGE + tile * TILEB + row * ROWB + seg * 16;
            const __half* src;
            int grow;
            if (tile == 0) { src = A1; grow = GATHER ? tks[row] : row0 + row; }
            else           { src = B1; grow = row; }
            cp16(sa, src + (size_t)grow * HDIM + kbase + seg * 8);
        }
    };

    float acc[4][4][4];
#pragma unroll
    for (int mi = 0; mi < 4; mi++)
#pragma unroll
        for (int ni = 0; ni < 4; ni++)
#pragma unroll
            for (int k = 0; k < 4; k++) acc[mi][ni][k] = 0.0f;

    issue(0, 0);  CP_COMMIT();
    issue(1, KC); CP_COMMIT();

    const int lm = lane & 15, lh = lane >> 4;
    const uint32_t a_off = (uint32_t)((warp_m * 64 + lm) * ROWB + lh * 16);
    const uint32_t b_off = (uint32_t)((warp_n * 32 + lm) * ROWB + lh * 16);

    for (int c = 0; c < NCK; c++) {
        CP_WAIT1();
        __syncthreads();
        const int buf = c & 1;
        const uint32_t sA1 = sb + buf * STAGE;
        const uint32_t sB1 = sA1 + TILEB;

#pragma unroll
        for (int kh = 0; kh < 4; kh++) {
            uint32_t a1[4][4], b1f[4][2];
#pragma unroll
            for (int mi = 0; mi < 4; mi++)
                ldsm4(a1[mi], sA1 + a_off + mi * (16 * ROWB) + kh * 32);
#pragma unroll
            for (int nt = 0; nt < 2; nt++) {
                uint32_t r[4];
                ldsm4(r, sB1 + b_off + nt * (16 * ROWB) + kh * 32);
                b1f[nt * 2][0] = r[0]; b1f[nt * 2][1] = r[2];
                b1f[nt * 2 + 1][0] = r[1]; b1f[nt * 2 + 1][1] = r[3];
            }
#pragma unroll
            for (int mi = 0; mi < 4; mi++)
#pragma unroll
                for (int ni = 0; ni < 4; ni++)
                    mma16816(acc[mi][ni], a1[mi], b1f[ni]);
        }
        __syncthreads();
        if (c + 2 < NCK) issue(buf, (c + 2) * KC);
        CP_COMMIT();
    }

    // ---------------- epilogue ----------------
    const int rbase = warp_m * 64 + (lane >> 2);
    const int cbase = warp_n * 32 + (lane & 3) * 2;
    if (GATHER) {
#pragma unroll
        for (int mi = 0; mi < 4; mi++) {
#pragma unroll
            for (int ni = 0; ni < 4; ni++) {
                const int r0 = rbase + mi * 16;
                const int cc = cbase + ni * 8;
                float v00 = acc[mi][ni][0] + sbias[cc];
                float v01 = acc[mi][ni][1] + sbias[cc + 1];
                float v10 = acc[mi][ni][2] + sbias[cc];
                float v11 = acc[mi][ni][3] + sbias[cc + 1];
                if (r0 < nrows) {
                    float* p = outg + (size_t)tks[r0] * HDIM + col0 + cc;
                    *(float2*)p = make_float2(v00, v01);
                }
                if (r0 + 8 < nrows) {
                    float* p = outg + (size_t)tks[r0 + 8] * HDIM + col0 + cc;
                    *(float2*)p = make_float2(v10, v11);
                }
            }
        }
    } else {
        // fused routing-score epilogue: relu(acc + b1) dot w2-slice -> atomics
#pragma unroll
        for (int mi = 0; mi < 4; mi++) {
#pragma unroll
            for (int ro = 0; ro < 2; ro++) {
                const int row = rbase + mi * 16 + ro * 8;
                float part[NEXP];
#pragma unroll
                for (int e = 0; e < NEXP; e++) part[e] = 0.0f;
#pragma unroll
                for (int ni = 0; ni < 4; ni++) {
                    const int cc = cbase + ni * 8;
                    float v0 = fmaxf(acc[mi][ni][ro * 2 + 0] + sbias[cc], 0.0f);
                    float v1 = fmaxf(acc[mi][ni][ro * 2 + 1] + sbias[cc + 1], 0.0f);
#pragma unroll
                    for (int e = 0; e < NEXP; e++)
                        part[e] = fmaf(v0, sw2[cc * NEXP + e],
                                       fmaf(v1, sw2[(cc + 1) * NEXP + e], part[e]));
                }
                // reduce across the 4 lanes of the quad (covers 8 cols per ni)
#pragma unroll
                for (int e = 0; e < NEXP; e++) {
                    part[e] += __shfl_xor_sync(0xffffffffu, part[e], 1);
                    part[e] += __shfl_xor_sync(0xffffffffu, part[e], 2);
                }
                if ((lane & 3) == 0) {
#pragma unroll
                    for (int e = 0; e < NEXP; e++)
                        atomicAdd(&g_score[(size_t)(row0 + row) * NEXP + e], part[e]);
                }
            }
        }
    }
}

// ---------------- argmax + counts + near-tie flagging ----------------
__global__ __launch_bounds__(256) void k_argmax(const float* __restrict__ b2) {
    const int t = blockIdx.x * 256 + threadIdx.x;
    if (t >= NTOK) return;
    const float* sr = g_score + (size_t)t * NEXP;
    int best = 0;
    float bv = sr[0] + b2[0], second = -1e30f;
#pragma unroll
    for (int e = 1; e < NEXP; e++) {
        float v = sr[e] + b2[e];
        if (v > bv) { second = bv; bv = v; best = e; }
        else if (v > second) second = v;
    }
    g_idx[t] = best;
    atomicAdd(&g_counts[best], 1);
    if (bv - second < GAP_THRESH) {
        int slot = atomicAdd(&g_nflag, 1);
        if (slot < MAXFLAG) g_flag[slot] = t;
    }
}

// ---------------- exact fp32 rescue (one block per flagged token, ILP4) ------
__global__ __launch_bounds__(256) void k_rescue(const float* __restrict__ X,
                                                const float* __restrict__ w1,
                                                const float* __restrict__ b1,
                                                const float* __restrict__ w2,
                                                const float* __restrict__ b2) {
    __shared__ float sx[HDIM];
    __shared__ float ssc[NEXP];
    const int tid = threadIdx.x;
    int n = g_nflag;
    if (n > MAXFLAG) n = MAXFLAG;
    for (int i = blockIdx.x; i < n; i += gridDim.x) {
        const int tok = g_flag[i];
        for (int k = tid; k < HDIM; k += 256) sx[k] = X[(size_t)tok * HDIM + k];
        if (tid < NEXP) ssc[tid] = 0.0f;
        __syncthreads();
        float sc[NEXP];
#pragma unroll
        for (int e = 0; e < NEXP; e++) sc[e] = 0.0f;
#pragma unroll
        for (int half = 0; half < 2; half++) {
            const int nc = tid + half * 256;
            float a0 = 0.f, a1 = 0.f, a2 = 0.f, a3 = 0.f;
#pragma unroll 4
            for (int k = 0; k < HDIM; k += 4) {
                a0 = fmaf(sx[k + 0], __ldg(&w1[(size_t)(k + 0) * MDIM + nc]), a0);
                a1 = fmaf(sx[k + 1], __ldg(&w1[(size_t)(k + 1) * MDIM + nc]), a1);
                a2 = fmaf(sx[k + 2], __ldg(&w1[(size_t)(k + 2) * MDIM + nc]), a2);
                a3 = fmaf(sx[k + 3], __ldg(&w1[(size_t)(k + 3) * MDIM + nc]), a3);
            }
            float a = fmaxf((a0 + a1) + (a2 + a3) + b1[nc], 0.0f);
#pragma unroll
            for (int e = 0; e < NEXP; e++) sc[e] = fmaf(a, w2[nc * NEXP + e], sc[e]);
        }
#pragma unroll
        for (int e = 0; e < NEXP; e++) {
#pragma unroll
            for (int off = 16; off; off >>= 1) sc[e] += __shfl_xor_sync(0xffffffffu, sc[e], off);
            if ((tid & 31) == 0) atomicAdd(&ssc[e], sc[e]);
        }
        __syncthreads();
        if (tid == 0) {
            int best = 0;
            float bv = ssc[0] + b2[0];
#pragma unroll
            for (int e = 1; e < NEXP; e++) {
                float v = ssc[e] + b2[e];
                if (v > bv) { bv = v; best = e; }
            }
            int old = g_idx[tok];
            if (best != old) {
                g_idx[tok] = best;
                atomicSub(&g_counts[old], 1);
                atomicAdd(&g_counts[best], 1);
            }
        }
        __syncthreads();
    }
}

// ---------------- scan + fill ----------------
__global__ void k_scan() {
    int s = 0;
    for (int e = 0; e < NEXP; e++) { g_base[e] = s; s += g_counts[e]; }
    int nt = 0;
    for (int e = 0; e < NEXP; e++) {
        int c = g_counts[e];
        for (int r = 0; r < c; r += 128) {
            g_tile_e[nt] = e;
            g_tile_r[nt] = g_base[e] + r;
            g_tile_n[nt] = (c - r) < 128 ? (c - r) : 128;
            nt++;
        }
    }
    g_numtiles = nt;
}
__global__ void k_fill() {
    int t = blockIdx.x * 256 + threadIdx.x;
    if (t < NTOK) {
        int e = g_idx[t];
        int r = atomicAdd(&g_cursor[e], 1);
        g_perm[g_base[e] + r] = t;
    }
}

// ---------------- launch ----------------
extern "C" void kernel_launch(void* const* d_in, const int* in_sizes, int n_in,
                              void* d_out, int out_size) {
    const float* X  = (const float*)d_in[0];
    const float* w1 = (const float*)d_in[1];
    const float* b1 = (const float*)d_in[2];
    const float* w2 = (const float*)d_in[3];
    const float* b2 = (const float*)d_in[4];
    const float* eW = (const float*)d_in[5];
    const float* eb = (const float*)d_in[6];
    float* out = (float*)d_out;

    const int DSM = 2 * 2 * TILEB;  // 73728
    cudaFuncSetAttribute(k_gemm_mma<false>, cudaFuncAttributeMaxDynamicSharedMemorySize, DSM);
    cudaFuncSetAttribute(k_gemm_mma<true>,  cudaFuncAttributeMaxDynamicSharedMemorySize, DSM);

    k_init<<<1, 32>>>();
    k_zeroscore<<<NTOK * NEXP / 4 / 256, 256>>>();
    k_convA<<<NTOK * HDIM / 1024, 256>>>(X);
    k_convW1<<<dim3(MDIM / 32, HDIM / 32, 1), dim3(32, 8)>>>(w1);
    k_convW2<<<dim3(HDIM / 32, HDIM / 32, NEXP), dim3(32, 8)>>>(eW);
    k_gemm_mma<false><<<dim3(NTOK / 128, MDIM / 128), 256, DSM>>>(b1, w2, nullptr);
    k_argmax<<<NTOK / 256, 256>>>(b2);
    k_rescue<<<256, 256>>>(X, w1, b1, w2, b2);
    k_scan<<<1, 1>>>();
    k_fill<<<NTOK / 256, 256>>>();
    k_gemm_mma<true><<<dim3(MAX_TILES, HDIM / 128), 256, DSM>>>(eb, nullptr, out);
}